// round 1
// baseline (speedup 1.0000x reference)
#include <cuda_runtime.h>
#include <math_constants.h>

#define BB   4
#define TT   2048
#define DD   512
#define NH   8
#define NKV  4
#define HD   64
#define NTOK (BB*TT)          // 8192

// ---------------- scratch (device globals: allocation-free) ----------------
__device__ float g_q[(size_t)NTOK * DD];        // [B*T, 8*64]
__device__ float g_k[(size_t)NTOK * NKV * HD];  // [B*T, 4*64]
__device__ float g_v[(size_t)NTOK * NKV * HD];
__device__ float g_y[(size_t)NTOK * DD];        // attention output

// ---------------------------------------------------------------------------
// SGEMM (NT): C[n, m] = sum_d A[n, d] * W[m, d],  A:[8192,512], W:[M,512]
// BM=BN=64, BK=32, 256 threads, 4x4 microtile. K-major SMEM tiles, +1 pad
// (conflict-free transposed stores, broadcast/2-way reads).
// ---------------------------------------------------------------------------
__global__ __launch_bounds__(256) void sgemm_nt(const float* __restrict__ A,
                                                const float* __restrict__ W,
                                                float* __restrict__ C, int M) {
    __shared__ float As[32][65];
    __shared__ float Ws[32][65];
    const int tid = threadIdx.x;
    const int tx = tid & 15, ty = tid >> 4;
    const int tx4 = tx << 2, ty4 = ty << 2;
    const int cb = blockIdx.x << 6;
    const int rb = blockIdx.y << 6;

    const float* Ap = A + (size_t)rb * DD;
    const float* Wp = W + (size_t)cb * DD;

    float acc[4][4] = {};

    for (int k0 = 0; k0 < DD; k0 += 32) {
#pragma unroll
        for (int i = 0; i < 2; i++) {
            int f4 = tid + (i << 8);          // 0..511
            int r  = f4 >> 3;                 // 0..63
            int c4 = f4 & 7;                  // 0..7
            int kk = c4 << 2;
            float4 av = *(const float4*)(Ap + (size_t)r * DD + k0 + (c4 << 2));
            float4 wv = *(const float4*)(Wp + (size_t)r * DD + k0 + (c4 << 2));
            As[kk + 0][r] = av.x; As[kk + 1][r] = av.y;
            As[kk + 2][r] = av.z; As[kk + 3][r] = av.w;
            Ws[kk + 0][r] = wv.x; Ws[kk + 1][r] = wv.y;
            Ws[kk + 2][r] = wv.z; Ws[kk + 3][r] = wv.w;
        }
        __syncthreads();
#pragma unroll 8
        for (int k = 0; k < 32; k++) {
            float a0 = As[k][ty4 + 0], a1 = As[k][ty4 + 1];
            float a2 = As[k][ty4 + 2], a3 = As[k][ty4 + 3];
            float b0 = Ws[k][tx4 + 0], b1 = Ws[k][tx4 + 1];
            float b2 = Ws[k][tx4 + 2], b3 = Ws[k][tx4 + 3];
            acc[0][0] += a0 * b0; acc[0][1] += a0 * b1; acc[0][2] += a0 * b2; acc[0][3] += a0 * b3;
            acc[1][0] += a1 * b0; acc[1][1] += a1 * b1; acc[1][2] += a1 * b2; acc[1][3] += a1 * b3;
            acc[2][0] += a2 * b0; acc[2][1] += a2 * b1; acc[2][2] += a2 * b2; acc[2][3] += a2 * b3;
            acc[3][0] += a3 * b0; acc[3][1] += a3 * b1; acc[3][2] += a3 * b2; acc[3][3] += a3 * b3;
        }
        __syncthreads();
    }
#pragma unroll
    for (int i = 0; i < 4; i++) {
        float4 o = make_float4(acc[i][0], acc[i][1], acc[i][2], acc[i][3]);
        *(float4*)(C + (size_t)(rb + ty4 + i) * M + cb + tx4) = o;
    }
}

// ---------------------------------------------------------------------------
// Fused RMSNorm + RoPE(16 dims) + gain (q) / RMSNorm + RoPE (k), in place.
// One warp per (token, head). Also folds softmax scale 1/8 into q.
// ---------------------------------------------------------------------------
__global__ __launch_bounds__(256) void normrope_kernel(const float* __restrict__ qg) {
    const int w    = (blockIdx.x * blockDim.x + threadIdx.x) >> 5;
    const int lane = threadIdx.x & 31;
    const int NQ = NTOK * NH;                 // 65536 q warps
    float* p;
    int pos;
    float mult;
    if (w < NQ) {
        int tok = w >> 3, hh = w & 7;
        p    = g_q + (size_t)tok * DD + hh * HD;
        pos  = tok & (TT - 1);
        mult = qg[hh] * 0.125f;               // gain * 1/sqrt(64)
    } else {
        int w2 = w - NQ;
        if (w2 >= NTOK * NKV) return;
        int tok = w2 >> 2, kv = w2 & 3;
        p    = g_k + (size_t)tok * (NKV * HD) + kv * HD;
        pos  = tok & (TT - 1);
        mult = 1.0f;
    }
    float v0 = p[lane];
    float v1 = p[lane + 32];
    float ss = v0 * v0 + v1 * v1;
#pragma unroll
    for (int o = 16; o > 0; o >>= 1) ss += __shfl_xor_sync(0xffffffffu, ss, o);
    const float rn = rsqrtf(ss * (1.0f / 64.0f) + 1.1920929e-7f);
    v0 *= rn; v1 *= rn;

    // RoPE on dims [0,16): pair (d, d+8), freq index d&7. lanes 0..7 hold x1, 8..15 x2.
    float other = __shfl_xor_sync(0xffffffffu, v0, 8);
    float r0 = v0;
    if (lane < 16) {
        int   fi   = lane & 7;
        float invf = powf(10000.0f, -(float)fi * 0.125f);
        float ang  = (float)pos * invf;
        float sn, cs;
        sincosf(ang, &sn, &cs);
        r0 = (lane < 8) ? (v0 * cs + other * sn) : (v0 * cs - other * sn);
    }
    p[lane]      = r0 * mult;
    p[lane + 32] = v1 * mult;
}

// ---------------------------------------------------------------------------
// Flash-style causal attention. Block = (q-tile of 64 rows, one (b,h)).
// 256 threads, 4x4 microtiles for both S=QK^T and O+=P*V. Online softmax.
// Heavy tiles (large qt) scheduled first via reversed blockIdx.x.
// ---------------------------------------------------------------------------
#define QSTR 68
#define PSTR 65
#define ATTN_SMEM ((3 * 64 * QSTR + 64 * PSTR) * 4)   // 68864 B

__global__ __launch_bounds__(256) void attn_kernel() {
    extern __shared__ float sm[];
    float* Qs = sm;                       // [d][row], stride 68
    float* Ks = sm + 64 * QSTR;           // [d][key], stride 68
    float* Vs = sm + 2 * 64 * QSTR;       // [key][d], stride 68
    float* Ps = sm + 3 * 64 * QSTR;       // [key][row], stride 65

    const int tid = threadIdx.x;
    const int tx = tid & 15, ty = tid >> 4;
    const int tx4 = tx << 2, ty4 = ty << 2;
    const int qt  = gridDim.x - 1 - blockIdx.x;   // heavy blocks first
    const int bh  = blockIdx.y;
    const int b   = bh >> 3, h = bh & 7, kvh = h >> 1;
    const float NEG_INF = -CUDART_INF_F;

    // load Q tile (transposed into d-major)
    const float* qbase = g_q + (size_t)(b * TT + qt * 64) * DD + h * HD;
#pragma unroll
    for (int i = 0; i < 4; i++) {
        int f4 = tid + (i << 8);
        int r = f4 >> 4, d4 = f4 & 15;
        float4 v = *(const float4*)(qbase + (size_t)r * DD + (d4 << 2));
        int d = d4 << 2;
        Qs[(d + 0) * QSTR + r] = v.x; Qs[(d + 1) * QSTR + r] = v.y;
        Qs[(d + 2) * QSTR + r] = v.z; Qs[(d + 3) * QSTR + r] = v.w;
    }

    float oacc[4][4] = {};
    float mrow[4] = {NEG_INF, NEG_INF, NEG_INF, NEG_INF};
    float lrow[4] = {};

    const float* kbase0 = g_k + ((size_t)(b * TT) * NKV + kvh) * HD;
    const float* vbase0 = g_v + ((size_t)(b * TT) * NKV + kvh) * HD;

    for (int kt = 0; kt <= qt; kt++) {
        __syncthreads();   // prior PV done before overwriting Ks/Vs/Ps (also covers Q load)
        const float* kb = kbase0 + (size_t)kt * 64 * (NKV * HD);
        const float* vb = vbase0 + (size_t)kt * 64 * (NKV * HD);
#pragma unroll
        for (int i = 0; i < 4; i++) {
            int f4 = tid + (i << 8);
            int r = f4 >> 4, d4 = f4 & 15;
            int d = d4 << 2;
            float4 kv = *(const float4*)(kb + (size_t)r * (NKV * HD) + (d4 << 2));
            Ks[(d + 0) * QSTR + r] = kv.x; Ks[(d + 1) * QSTR + r] = kv.y;
            Ks[(d + 2) * QSTR + r] = kv.z; Ks[(d + 3) * QSTR + r] = kv.w;
            float4 vv = *(const float4*)(vb + (size_t)r * (NKV * HD) + (d4 << 2));
            *(float4*)(Vs + r * QSTR + d) = vv;
        }
        __syncthreads();

        // S = Q K^T  (scale+gain already folded into q)
        float sacc[4][4] = {};
#pragma unroll 8
        for (int d = 0; d < 64; d++) {
            float qv[4], kv[4];
            *(float4*)qv = *(const float4*)(Qs + d * QSTR + ty4);
            *(float4*)kv = *(const float4*)(Ks + d * QSTR + tx4);
#pragma unroll
            for (int ii = 0; ii < 4; ii++)
#pragma unroll
                for (int jj = 0; jj < 4; jj++)
                    sacc[ii][jj] += qv[ii] * kv[jj];
        }

        const bool diag = (kt == qt);
#pragma unroll
        for (int ii = 0; ii < 4; ii++) {
            if (diag) {
#pragma unroll
                for (int jj = 0; jj < 4; jj++)
                    if (tx4 + jj > ty4 + ii) sacc[ii][jj] = NEG_INF;
            }
            float mr = fmaxf(fmaxf(sacc[ii][0], sacc[ii][1]),
                             fmaxf(sacc[ii][2], sacc[ii][3]));
#pragma unroll
            for (int o = 8; o > 0; o >>= 1)
                mr = fmaxf(mr, __shfl_xor_sync(0xffffffffu, mr, o));
            float mn    = fmaxf(mrow[ii], mr);
            float alpha = expf(mrow[ii] - mn);
            mrow[ii]    = mn;
            float rs = 0.0f;
#pragma unroll
            for (int jj = 0; jj < 4; jj++) {
                float pe = expf(sacc[ii][jj] - mn);
                rs += pe;
                Ps[(tx4 + jj) * PSTR + ty4 + ii] = pe;
            }
#pragma unroll
            for (int o = 8; o > 0; o >>= 1)
                rs += __shfl_xor_sync(0xffffffffu, rs, o);
            lrow[ii] = lrow[ii] * alpha + rs;
#pragma unroll
            for (int jj = 0; jj < 4; jj++) oacc[ii][jj] *= alpha;
        }
        __syncthreads();   // Ps visible to all

        // O += P * V
#pragma unroll 8
        for (int j = 0; j < 64; j++) {
            float vv[4];
            *(float4*)vv = *(const float4*)(Vs + j * QSTR + tx4);
            float p0 = Ps[j * PSTR + ty4 + 0];
            float p1 = Ps[j * PSTR + ty4 + 1];
            float p2 = Ps[j * PSTR + ty4 + 2];
            float p3 = Ps[j * PSTR + ty4 + 3];
#pragma unroll
            for (int jj = 0; jj < 4; jj++) {
                oacc[0][jj] += p0 * vv[jj];
                oacc[1][jj] += p1 * vv[jj];
                oacc[2][jj] += p2 * vv[jj];
                oacc[3][jj] += p3 * vv[jj];
            }
        }
    }

#pragma unroll
    for (int ii = 0; ii < 4; ii++) {
        float inv = 1.0f / lrow[ii];
        float4 o = make_float4(oacc[ii][0] * inv, oacc[ii][1] * inv,
                               oacc[ii][2] * inv, oacc[ii][3] * inv);
        *(float4*)(g_y + (size_t)(b * TT + qt * 64 + ty4 + ii) * DD + h * HD + tx4) = o;
    }
}

// ---------------------------------------------------------------------------
extern "C" void kernel_launch(void* const* d_in, const int* in_sizes, int n_in,
                              void* d_out, int out_size) {
    (void)in_sizes; (void)n_in; (void)out_size;
    const float* x      = (const float*)d_in[0];
    const float* w_q    = (const float*)d_in[1];
    const float* w_k    = (const float*)d_in[2];
    const float* w_v    = (const float*)d_in[3];
    const float* w_proj = (const float*)d_in[4];
    const float* q_gain = (const float*)d_in[5];
    float* out = (float*)d_out;

    cudaFuncSetAttribute(attn_kernel, cudaFuncAttributeMaxDynamicSharedMemorySize,
                         ATTN_SMEM);

    void* p;
    cudaGetSymbolAddress(&p, g_q); float* gq = (float*)p;
    cudaGetSymbolAddress(&p, g_k); float* gk = (float*)p;
    cudaGetSymbolAddress(&p, g_v); float* gv = (float*)p;
    cudaGetSymbolAddress(&p, g_y); float* gy = (float*)p;

    // QKV projections (raw)
    sgemm_nt<<<dim3(8, 128), 256>>>(x, w_q, gq, 512);
    sgemm_nt<<<dim3(4, 128), 256>>>(x, w_k, gk, 256);
    sgemm_nt<<<dim3(4, 128), 256>>>(x, w_v, gv, 256);

    // RMSNorm + RoPE + gain/scale, in place on g_q / g_k
    normrope_kernel<<<(NTOK * (NH + NKV)) / 8, 256>>>(q_gain);

    // Causal attention -> g_y
    attn_kernel<<<dim3(TT / 64, BB * NH), 256, ATTN_SMEM>>>();

    // Output projection
    sgemm_nt<<<dim3(8, 128), 256>>>(gy, w_proj, out, 512);
}

// round 4
// speedup vs baseline: 1.5727x; 1.5727x over previous
#include <cuda_runtime.h>
#include <math_constants.h>
#include <cstdint>

#define BB   4
#define TT   2048
#define DD   512
#define NH   8
#define NKV  4
#define HD   64
#define NTOK (BB*TT)          // 8192

// ---------------- scratch (device globals: allocation-free) ----------------
__device__ float g_q[(size_t)NTOK * DD];        // [B*T, 8*64]
__device__ float g_k[(size_t)NTOK * NKV * HD];  // [B*T, 4*64]
__device__ float g_v[(size_t)NTOK * NKV * HD];
__device__ float g_y[(size_t)NTOK * DD];        // attention output

// ------------------------------ helpers ------------------------------------
__device__ __forceinline__ uint32_t f2tf(float f) {
    uint32_t u;
    asm("cvt.rna.tf32.f32 %0, %1;" : "=r"(u) : "f"(f));
    return u;
}
__device__ __forceinline__ float f2tff(float f) { return __uint_as_float(f2tf(f)); }

// split v into tf32 big + tf32 small (3xTF32 decomposition)
__device__ __forceinline__ void splitf(float v, float& b, float& s) {
    b = f2tff(v);
    s = f2tff(v - b);
}

__device__ __forceinline__ void mma_tf32(float c[4], uint32_t a0, uint32_t a1,
                                         uint32_t a2, uint32_t a3,
                                         uint32_t b0, uint32_t b1) {
    asm volatile(
        "mma.sync.aligned.m16n8k8.row.col.f32.tf32.tf32.f32 "
        "{%0,%1,%2,%3},{%4,%5,%6,%7},{%8,%9},{%0,%1,%2,%3};"
        : "+f"(c[0]), "+f"(c[1]), "+f"(c[2]), "+f"(c[3])
        : "r"(a0), "r"(a1), "r"(a2), "r"(a3), "r"(b0), "r"(b1));
}

// ---------------------------------------------------------------------------
// 3xTF32 SGEMM (NT): C[n,m] = sum_d A[n,d] * W[m,d].  BM=BN=64, BK=32,
// 256 threads (8 warps), warp grid 2x4, warp tile 32x16 (2x2 mma tiles).
// big/small tiles in smem, converted once per element.
// ---------------------------------------------------------------------------
__global__ __launch_bounds__(256) void sgemm_tf32(const float* __restrict__ A,
                                                  const float* __restrict__ W,
                                                  float* __restrict__ C, int M) {
    __shared__ float Ab[64][36], Asm[64][36];
    __shared__ float Wb[64][36], Wsm[64][36];
    const int tid  = threadIdx.x;
    const int warp = tid >> 5, lane = tid & 31;
    const int gid = lane >> 2, tig = lane & 3;
    const int wm = warp >> 2, wn = warp & 3;          // 2 x 4
    const int rb = blockIdx.y << 6, cb = blockIdx.x << 6;

    const float* Ap = A + (size_t)rb * DD;
    const float* Wp = W + (size_t)cb * DD;

    float acc[2][2][4] = {};

    for (int k0 = 0; k0 < DD; k0 += 32) {
#pragma unroll
        for (int i = 0; i < 2; i++) {
            int idx = tid + (i << 8);          // 0..511
            int r = idx >> 3, c4 = idx & 7;
            float4 av = *(const float4*)(Ap + (size_t)r * DD + k0 + (c4 << 2));
            float4 wv = *(const float4*)(Wp + (size_t)r * DD + k0 + (c4 << 2));
            float4 abv, asv, wbv, wsv;
            splitf(av.x, abv.x, asv.x); splitf(av.y, abv.y, asv.y);
            splitf(av.z, abv.z, asv.z); splitf(av.w, abv.w, asv.w);
            splitf(wv.x, wbv.x, wsv.x); splitf(wv.y, wbv.y, wsv.y);
            splitf(wv.z, wbv.z, wsv.z); splitf(wv.w, wbv.w, wsv.w);
            *(float4*)&Ab[r][c4 << 2]  = abv;
            *(float4*)&Asm[r][c4 << 2] = asv;
            *(float4*)&Wb[r][c4 << 2]  = wbv;
            *(float4*)&Wsm[r][c4 << 2] = wsv;
        }
        __syncthreads();
#pragma unroll
        for (int ks = 0; ks < 4; ks++) {
            uint32_t ab[2][4], as_[2][4];
#pragma unroll
            for (int mt = 0; mt < 2; mt++) {
                int row = (wm << 5) + (mt << 4) + gid;
                int col = (ks << 3) + tig;
                ab[mt][0]  = __float_as_uint(Ab[row][col]);
                ab[mt][1]  = __float_as_uint(Ab[row + 8][col]);
                ab[mt][2]  = __float_as_uint(Ab[row][col + 4]);
                ab[mt][3]  = __float_as_uint(Ab[row + 8][col + 4]);
                as_[mt][0] = __float_as_uint(Asm[row][col]);
                as_[mt][1] = __float_as_uint(Asm[row + 8][col]);
                as_[mt][2] = __float_as_uint(Asm[row][col + 4]);
                as_[mt][3] = __float_as_uint(Asm[row + 8][col + 4]);
            }
#pragma unroll
            for (int nt = 0; nt < 2; nt++) {
                int nrow = (wn << 4) + (nt << 3) + gid;
                int col  = (ks << 3) + tig;
                uint32_t bb0 = __float_as_uint(Wb[nrow][col]);
                uint32_t bb1 = __float_as_uint(Wb[nrow][col + 4]);
                uint32_t bs0 = __float_as_uint(Wsm[nrow][col]);
                uint32_t bs1 = __float_as_uint(Wsm[nrow][col + 4]);
#pragma unroll
                for (int mt = 0; mt < 2; mt++) {
                    mma_tf32(acc[mt][nt], ab[mt][0], ab[mt][1], ab[mt][2], ab[mt][3], bb0, bb1);
                    mma_tf32(acc[mt][nt], ab[mt][0], ab[mt][1], ab[mt][2], ab[mt][3], bs0, bs1);
                    mma_tf32(acc[mt][nt], as_[mt][0], as_[mt][1], as_[mt][2], as_[mt][3], bb0, bb1);
                }
            }
        }
        __syncthreads();
    }
#pragma unroll
    for (int mt = 0; mt < 2; mt++)
#pragma unroll
        for (int nt = 0; nt < 2; nt++) {
            int row = rb + (wm << 5) + (mt << 4) + gid;
            int col = cb + (wn << 4) + (nt << 3) + (tig << 1);
            *(float2*)(C + (size_t)row * M + col)       = make_float2(acc[mt][nt][0], acc[mt][nt][1]);
            *(float2*)(C + (size_t)(row + 8) * M + col) = make_float2(acc[mt][nt][2], acc[mt][nt][3]);
        }
}

// ---------------------------------------------------------------------------
// Fused RMSNorm + RoPE(16 dims) + gain (q) / RMSNorm + RoPE (k), in place.
// One warp per (token, head). Folds softmax scale 1/8 into q.
// ---------------------------------------------------------------------------
__global__ __launch_bounds__(256) void normrope_kernel(const float* __restrict__ qg) {
    const int w    = (blockIdx.x * blockDim.x + threadIdx.x) >> 5;
    const int lane = threadIdx.x & 31;
    const int NQ = NTOK * NH;
    float* p;
    int pos;
    float mult;
    if (w < NQ) {
        int tok = w >> 3, hh = w & 7;
        p    = g_q + (size_t)tok * DD + hh * HD;
        pos  = tok & (TT - 1);
        mult = qg[hh] * 0.125f;
    } else {
        int w2 = w - NQ;
        if (w2 >= NTOK * NKV) return;
        int tok = w2 >> 2, kv = w2 & 3;
        p    = g_k + (size_t)tok * (NKV * HD) + kv * HD;
        pos  = tok & (TT - 1);
        mult = 1.0f;
    }
    float v0 = p[lane];
    float v1 = p[lane + 32];
    float ss = v0 * v0 + v1 * v1;
#pragma unroll
    for (int o = 16; o > 0; o >>= 1) ss += __shfl_xor_sync(0xffffffffu, ss, o);
    const float rn = rsqrtf(ss * (1.0f / 64.0f) + 1.1920929e-7f);
    v0 *= rn; v1 *= rn;

    float other = __shfl_xor_sync(0xffffffffu, v0, 8);
    float r0 = v0;
    if (lane < 16) {
        int   fi   = lane & 7;
        float invf = powf(10000.0f, -(float)fi * 0.125f);
        float ang  = (float)pos * invf;
        float sn, cs;
        sincosf(ang, &sn, &cs);
        r0 = (lane < 8) ? (v0 * cs + other * sn) : (v0 * cs - other * sn);
    }
    p[lane]      = r0 * mult;
    p[lane + 32] = v1 * mult;
}

// ---------------------------------------------------------------------------
// Flash attention, 3xTF32 tensor cores.
// Block: 64 q-rows x one (b,h). 128 threads (4 warps); warp owns 16 rows.
// K/V stored as big/small smem pairs; Q big/small register-resident;
// P stored fp32, split at fragment load (amortized over 8 n-tiles).
// ---------------------------------------------------------------------------
#define AQ 68   // K / P row stride (floats)
#define AV 72   // V row stride
#define ATTN_SMEM ((2 * 64 * AQ + 2 * 64 * AV + 64 * AQ) * 4)   // 89088 B

__global__ __launch_bounds__(128) void attn_tf32() {
    extern __shared__ float sm[];
    float* Ksb = sm;                        // [key][d] big
    float* Kss = Ksb + 64 * AQ;             // [key][d] small
    float* Vsb = Kss + 64 * AQ;             // [key][d] big
    float* Vss = Vsb + 64 * AV;             // [key][d] small
    float* Ps  = Vss + 64 * AV;             // [row][key] fp32

    const int tid  = threadIdx.x;
    const int warp = tid >> 5, lane = tid & 31;
    const int gid = lane >> 2, tig = lane & 3;
    const int rowbase = warp << 4;

    const int qt  = gridDim.x - 1 - blockIdx.x;    // heavy tiles first
    const int bh  = blockIdx.y;
    const int b   = bh >> 3, h = bh & 7, kvh = h >> 1;
    const float NEG = -CUDART_INF_F;

    // Q fragments (16 rows x 64 d per warp), big/small register-resident
    uint32_t qb[8][4], qs[8][4];
    const float* qptr = g_q + (size_t)(b * TT + qt * 64 + rowbase) * DD + h * HD;
#pragma unroll
    for (int ks = 0; ks < 8; ks++) {
        int col = (ks << 3) + tig;
        float v0 = qptr[(size_t)gid * DD + col];
        float v1 = qptr[(size_t)(gid + 8) * DD + col];
        float v2 = qptr[(size_t)gid * DD + col + 4];
        float v3 = qptr[(size_t)(gid + 8) * DD + col + 4];
        float bb, ss_;
        splitf(v0, bb, ss_); qb[ks][0] = __float_as_uint(bb); qs[ks][0] = __float_as_uint(ss_);
        splitf(v1, bb, ss_); qb[ks][1] = __float_as_uint(bb); qs[ks][1] = __float_as_uint(ss_);
        splitf(v2, bb, ss_); qb[ks][2] = __float_as_uint(bb); qs[ks][2] = __float_as_uint(ss_);
        splitf(v3, bb, ss_); qb[ks][3] = __float_as_uint(bb); qs[ks][3] = __float_as_uint(ss_);
    }

    float oacc[8][4] = {};
    float m0 = NEG, m1 = NEG, l0 = 0.0f, l1 = 0.0f;

    const float* kbase = g_k + ((size_t)(b * TT) * NKV + kvh) * HD;
    const float* vbase = g_v + ((size_t)(b * TT) * NKV + kvh) * HD;

    for (int kt = 0; kt <= qt; kt++) {
        __syncthreads();                           // tiles free to overwrite
        const float* kp = kbase + (size_t)kt * 64 * (NKV * HD);
        const float* vp = vbase + (size_t)kt * 64 * (NKV * HD);
#pragma unroll
        for (int i = 0; i < 8; i++) {
            int idx = tid + (i << 7);
            int r = idx >> 4, c4 = idx & 15;
            float4 kv4 = *(const float4*)(kp + (size_t)r * (NKV * HD) + (c4 << 2));
            float4 vv4 = *(const float4*)(vp + (size_t)r * (NKV * HD) + (c4 << 2));
            float4 kb4, ks4, vb4, vs4;
            splitf(kv4.x, kb4.x, ks4.x); splitf(kv4.y, kb4.y, ks4.y);
            splitf(kv4.z, kb4.z, ks4.z); splitf(kv4.w, kb4.w, ks4.w);
            splitf(vv4.x, vb4.x, vs4.x); splitf(vv4.y, vb4.y, vs4.y);
            splitf(vv4.z, vb4.z, vs4.z); splitf(vv4.w, vb4.w, vs4.w);
            *(float4*)&Ksb[r * AQ + (c4 << 2)] = kb4;
            *(float4*)&Kss[r * AQ + (c4 << 2)] = ks4;
            *(float4*)&Vsb[r * AV + (c4 << 2)] = vb4;
            *(float4*)&Vss[r * AV + (c4 << 2)] = vs4;
        }
        __syncthreads();

        // S = Q K^T  (3xTF32)
        float sacc[8][4] = {};
#pragma unroll
        for (int ks = 0; ks < 8; ks++) {
            int col = (ks << 3) + tig;
#pragma unroll
            for (int nt = 0; nt < 8; nt++) {
                int key = (nt << 3) + gid;
                uint32_t kb0 = __float_as_uint(Ksb[key * AQ + col]);
                uint32_t kb1 = __float_as_uint(Ksb[key * AQ + col + 4]);
                uint32_t ks0 = __float_as_uint(Kss[key * AQ + col]);
                uint32_t ks1 = __float_as_uint(Kss[key * AQ + col + 4]);
                mma_tf32(sacc[nt], qb[ks][0], qb[ks][1], qb[ks][2], qb[ks][3], kb0, kb1);
                mma_tf32(sacc[nt], qb[ks][0], qb[ks][1], qb[ks][2], qb[ks][3], ks0, ks1);
                mma_tf32(sacc[nt], qs[ks][0], qs[ks][1], qs[ks][2], qs[ks][3], kb0, kb1);
            }
        }

        if (kt == qt) {                            // causal mask on diagonal tile
            int r0 = rowbase + gid, r1 = r0 + 8;
#pragma unroll
            for (int nt = 0; nt < 8; nt++) {
                int c0 = (nt << 3) + (tig << 1), c1 = c0 + 1;
                if (c0 > r0) sacc[nt][0] = NEG;
                if (c1 > r0) sacc[nt][1] = NEG;
                if (c0 > r1) sacc[nt][2] = NEG;
                if (c1 > r1) sacc[nt][3] = NEG;
            }
        }

        // online softmax (rows rowbase+gid and rowbase+gid+8)
        float mt0 = NEG, mt1 = NEG;
#pragma unroll
        for (int nt = 0; nt < 8; nt++) {
            mt0 = fmaxf(mt0, fmaxf(sacc[nt][0], sacc[nt][1]));
            mt1 = fmaxf(mt1, fmaxf(sacc[nt][2], sacc[nt][3]));
        }
        mt0 = fmaxf(mt0, __shfl_xor_sync(0xffffffffu, mt0, 1));
        mt0 = fmaxf(mt0, __shfl_xor_sync(0xffffffffu, mt0, 2));
        mt1 = fmaxf(mt1, __shfl_xor_sync(0xffffffffu, mt1, 1));
        mt1 = fmaxf(mt1, __shfl_xor_sync(0xffffffffu, mt1, 2));

        float mn0 = fmaxf(m0, mt0), mn1 = fmaxf(m1, mt1);
        float al0 = __expf(m0 - mn0), al1 = __expf(m1 - mn1);
        m0 = mn0; m1 = mn1;

        float rs0 = 0.0f, rs1 = 0.0f;
        int pr0 = (rowbase + gid) * AQ, pr1 = pr0 + 8 * AQ;
#pragma unroll
        for (int nt = 0; nt < 8; nt++) {
            float p0 = __expf(sacc[nt][0] - m0);
            float p1 = __expf(sacc[nt][1] - m0);
            float p2 = __expf(sacc[nt][2] - m1);
            float p3 = __expf(sacc[nt][3] - m1);
            rs0 += p0 + p1;
            rs1 += p2 + p3;
            int c = (nt << 3) + (tig << 1);
            *(float2*)&Ps[pr0 + c] = make_float2(p0, p1);
            *(float2*)&Ps[pr1 + c] = make_float2(p2, p3);
        }
        rs0 += __shfl_xor_sync(0xffffffffu, rs0, 1);
        rs0 += __shfl_xor_sync(0xffffffffu, rs0, 2);
        rs1 += __shfl_xor_sync(0xffffffffu, rs1, 1);
        rs1 += __shfl_xor_sync(0xffffffffu, rs1, 2);
        l0 = l0 * al0 + rs0;
        l1 = l1 * al1 + rs1;
#pragma unroll
        for (int nt = 0; nt < 8; nt++) {
            oacc[nt][0] *= al0; oacc[nt][1] *= al0;
            oacc[nt][2] *= al1; oacc[nt][3] *= al1;
        }
        __syncwarp();                              // Ps write -> read (warp-local)

        // O += P V  (3xTF32; P split amortized per ks)
#pragma unroll
        for (int ks = 0; ks < 8; ks++) {
            int kc = (ks << 3) + tig;
            float p0 = Ps[pr0 + kc];
            float p1 = Ps[pr1 + kc];
            float p2 = Ps[pr0 + kc + 4];
            float p3 = Ps[pr1 + kc + 4];
            float bb, ss_;
            uint32_t pb[4], psm[4];
            splitf(p0, bb, ss_); pb[0] = __float_as_uint(bb); psm[0] = __float_as_uint(ss_);
            splitf(p1, bb, ss_); pb[1] = __float_as_uint(bb); psm[1] = __float_as_uint(ss_);
            splitf(p2, bb, ss_); pb[2] = __float_as_uint(bb); psm[2] = __float_as_uint(ss_);
            splitf(p3, bb, ss_); pb[3] = __float_as_uint(bb); psm[3] = __float_as_uint(ss_);
#pragma unroll
            for (int nt = 0; nt < 8; nt++) {
                int d = (nt << 3) + gid;
                uint32_t vb0 = __float_as_uint(Vsb[kc * AV + d]);
                uint32_t vb1 = __float_as_uint(Vsb[(kc + 4) * AV + d]);
                uint32_t vs0 = __float_as_uint(Vss[kc * AV + d]);
                uint32_t vs1 = __float_as_uint(Vss[(kc + 4) * AV + d]);
                mma_tf32(oacc[nt], pb[0], pb[1], pb[2], pb[3], vb0, vb1);
                mma_tf32(oacc[nt], pb[0], pb[1], pb[2], pb[3], vs0, vs1);
                mma_tf32(oacc[nt], psm[0], psm[1], psm[2], psm[3], vb0, vb1);
            }
        }
    }

    float inv0 = 1.0f / l0, inv1 = 1.0f / l1;
    float* yp = g_y + (size_t)(b * TT + qt * 64) * DD + h * HD;
    int r0 = rowbase + gid, r1 = r0 + 8;
#pragma unroll
    for (int nt = 0; nt < 8; nt++) {
        int c = (nt << 3) + (tig << 1);
        *(float2*)(yp + (size_t)r0 * DD + c) =
            make_float2(oacc[nt][0] * inv0, oacc[nt][1] * inv0);
        *(float2*)(yp + (size_t)r1 * DD + c) =
            make_float2(oacc[nt][2] * inv1, oacc[nt][3] * inv1);
    }
}

// ---------------------------------------------------------------------------
extern "C" void kernel_launch(void* const* d_in, const int* in_sizes, int n_in,
                              void* d_out, int out_size) {
    (void)in_sizes; (void)n_in; (void)out_size;
    const float* x      = (const float*)d_in[0];
    const float* w_q    = (const float*)d_in[1];
    const float* w_k    = (const float*)d_in[2];
    const float* w_v    = (const float*)d_in[3];
    const float* w_proj = (const float*)d_in[4];
    const float* q_gain = (const float*)d_in[5];
    float* out = (float*)d_out;

    cudaFuncSetAttribute(attn_tf32, cudaFuncAttributeMaxDynamicSharedMemorySize,
                         ATTN_SMEM);

    void* p;
    cudaGetSymbolAddress(&p, g_q); float* gq = (float*)p;
    cudaGetSymbolAddress(&p, g_k); float* gk = (float*)p;
    cudaGetSymbolAddress(&p, g_v); float* gv = (float*)p;
    cudaGetSymbolAddress(&p, g_y); float* gy = (float*)p;

    sgemm_tf32<<<dim3(8, 128), 256>>>(x, w_q, gq, 512);
    sgemm_tf32<<<dim3(4, 128), 256>>>(x, w_k, gk, 256);
    sgemm_tf32<<<dim3(4, 128), 256>>>(x, w_v, gv, 256);

    normrope_kernel<<<(NTOK * (NH + NKV)) / 8, 256>>>(q_gain);

    attn_tf32<<<dim3(TT / 64, BB * NH), 128, ATTN_SMEM>>>();

    sgemm_tf32<<<dim3(8, 128), 256>>>(gy, w_proj, out, 512);
}

// round 6
// speedup vs baseline: 2.8234x; 1.7953x over previous
#include <cuda_runtime.h>
#include <cuda_fp16.h>
#include <math_constants.h>
#include <cstdint>

#define BB   4
#define TT   2048
#define DD   512
#define NH   8
#define NKV  4
#define HD   64
#define NTOK (BB*TT)          // 8192

// ---------------- scratch (device globals: allocation-free) ----------------
__device__ float g_q[(size_t)NTOK * DD];
__device__ float g_k[(size_t)NTOK * NKV * HD];
__device__ float g_v[(size_t)NTOK * NKV * HD];
__device__ float g_y[(size_t)NTOK * DD];

// ------------------------------ helpers ------------------------------------
// split (x,y) into fp16 big/small packed half2 pairs (fp16x3 decomposition)
__device__ __forceinline__ void split2(float x, float y, uint32_t& b, uint32_t& s) {
    __half hbx = __float2half_rn(x);
    __half hby = __float2half_rn(y);
    float rx = x - __half2float(hbx);
    float ry = y - __half2float(hby);
    __half2 hb = __halves2half2(hbx, hby);
    __half2 hs = __halves2half2(__float2half_rn(rx), __float2half_rn(ry));
    b = *reinterpret_cast<uint32_t*>(&hb);
    s = *reinterpret_cast<uint32_t*>(&hs);
}

__device__ __forceinline__ void mma_f16(float c[4], uint32_t a0, uint32_t a1,
                                        uint32_t a2, uint32_t a3,
                                        uint32_t b0, uint32_t b1) {
    asm volatile(
        "mma.sync.aligned.m16n8k16.row.col.f32.f16.f16.f32 "
        "{%0,%1,%2,%3},{%4,%5,%6,%7},{%8,%9},{%0,%1,%2,%3};"
        : "+f"(c[0]), "+f"(c[1]), "+f"(c[2]), "+f"(c[3])
        : "r"(a0), "r"(a1), "r"(a2), "r"(a3), "r"(b0), "r"(b1));
}

// ---------------------------------------------------------------------------
// fp16x3 SGEMM (NT): C[n,m] = sum_d A[n,d]*W[m,d].  BM=BN=64, BK=32,
// 256 threads (8 warps), warp grid 2x4, warp tile 32x16 (2x2 mma tiles).
// smem tiles: [row][kpair] half2, stride 20 (4*odd -> conflict-free frags).
// ---------------------------------------------------------------------------
__global__ __launch_bounds__(256) void sgemm_f16(const float* __restrict__ A,
                                                 const float* __restrict__ W,
                                                 float* __restrict__ C, int M) {
    __shared__ uint32_t Ab[64][20], As_[64][20];
    __shared__ uint32_t Wb[64][20], Ws_[64][20];
    const int tid  = threadIdx.x;
    const int warp = tid >> 5, lane = tid & 31;
    const int gid = lane >> 2, tig = lane & 3;
    const int wm = warp >> 2, wn = warp & 3;
    const int rb = blockIdx.y << 6, cb = blockIdx.x << 6;

    const float* Ap = A + (size_t)rb * DD;
    const float* Wp = W + (size_t)cb * DD;

    float acc[2][2][4] = {};

    for (int k0 = 0; k0 < DD; k0 += 32) {
#pragma unroll
        for (int i = 0; i < 2; i++) {
            int idx = tid + (i << 8);
            int r = idx >> 3, c4 = idx & 7;
            float4 av = *(const float4*)(Ap + (size_t)r * DD + k0 + (c4 << 2));
            float4 wv = *(const float4*)(Wp + (size_t)r * DD + k0 + (c4 << 2));
            uint32_t b0, s0, b1, s1;
            split2(av.x, av.y, b0, s0); split2(av.z, av.w, b1, s1);
            *(uint2*)&Ab[r][c4 << 1]  = make_uint2(b0, b1);
            *(uint2*)&As_[r][c4 << 1] = make_uint2(s0, s1);
            split2(wv.x, wv.y, b0, s0); split2(wv.z, wv.w, b1, s1);
            *(uint2*)&Wb[r][c4 << 1]  = make_uint2(b0, b1);
            *(uint2*)&Ws_[r][c4 << 1] = make_uint2(s0, s1);
        }
        __syncthreads();
#pragma unroll
        for (int ks = 0; ks < 2; ks++) {
            int dp = (ks << 3) + tig;
            uint32_t ab[2][4], as[2][4];
#pragma unroll
            for (int mt = 0; mt < 2; mt++) {
                int row = (wm << 5) + (mt << 4) + gid;
                ab[mt][0] = Ab[row][dp];      ab[mt][1] = Ab[row + 8][dp];
                ab[mt][2] = Ab[row][dp + 4];  ab[mt][3] = Ab[row + 8][dp + 4];
                as[mt][0] = As_[row][dp];     as[mt][1] = As_[row + 8][dp];
                as[mt][2] = As_[row][dp + 4]; as[mt][3] = As_[row + 8][dp + 4];
            }
#pragma unroll
            for (int nt = 0; nt < 2; nt++) {
                int nrow = (wn << 4) + (nt << 3) + gid;
                uint32_t bb0 = Wb[nrow][dp],  bb1 = Wb[nrow][dp + 4];
                uint32_t bs0 = Ws_[nrow][dp], bs1 = Ws_[nrow][dp + 4];
#pragma unroll
                for (int mt = 0; mt < 2; mt++) {
                    mma_f16(acc[mt][nt], ab[mt][0], ab[mt][1], ab[mt][2], ab[mt][3], bb0, bb1);
                    mma_f16(acc[mt][nt], ab[mt][0], ab[mt][1], ab[mt][2], ab[mt][3], bs0, bs1);
                    mma_f16(acc[mt][nt], as[mt][0], as[mt][1], as[mt][2], as[mt][3], bb0, bb1);
                }
            }
        }
        __syncthreads();
    }
#pragma unroll
    for (int mt = 0; mt < 2; mt++)
#pragma unroll
        for (int nt = 0; nt < 2; nt++) {
            int row = rb + (wm << 5) + (mt << 4) + gid;
            int col = cb + (wn << 4) + (nt << 3) + (tig << 1);
            *(float2*)(C + (size_t)row * M + col)       = make_float2(acc[mt][nt][0], acc[mt][nt][1]);
            *(float2*)(C + (size_t)(row + 8) * M + col) = make_float2(acc[mt][nt][2], acc[mt][nt][3]);
        }
}

// ---------------------------------------------------------------------------
// Fused RMSNorm + RoPE + gain (q) / RMSNorm + RoPE (k), in place.
// ---------------------------------------------------------------------------
__global__ __launch_bounds__(256) void normrope_kernel(const float* __restrict__ qg) {
    const int w    = (blockIdx.x * blockDim.x + threadIdx.x) >> 5;
    const int lane = threadIdx.x & 31;
    const int NQ = NTOK * NH;
    float* p;
    int pos;
    float mult;
    if (w < NQ) {
        int tok = w >> 3, hh = w & 7;
        p    = g_q + (size_t)tok * DD + hh * HD;
        pos  = tok & (TT - 1);
        mult = qg[hh] * 0.125f;
    } else {
        int w2 = w - NQ;
        if (w2 >= NTOK * NKV) return;
        int tok = w2 >> 2, kv = w2 & 3;
        p    = g_k + (size_t)tok * (NKV * HD) + kv * HD;
        pos  = tok & (TT - 1);
        mult = 1.0f;
    }
    float v0 = p[lane];
    float v1 = p[lane + 32];
    float ss = v0 * v0 + v1 * v1;
#pragma unroll
    for (int o = 16; o > 0; o >>= 1) ss += __shfl_xor_sync(0xffffffffu, ss, o);
    const float rn = rsqrtf(ss * (1.0f / 64.0f) + 1.1920929e-7f);
    v0 *= rn; v1 *= rn;

    float other = __shfl_xor_sync(0xffffffffu, v0, 8);
    float r0 = v0;
    if (lane < 16) {
        int   fi   = lane & 7;
        float invf = powf(10000.0f, -(float)fi * 0.125f);
        float ang  = (float)pos * invf;
        float sn, cs;
        sincosf(ang, &sn, &cs);
        r0 = (lane < 8) ? (v0 * cs + other * sn) : (v0 * cs - other * sn);
    }
    p[lane]      = r0 * mult;
    p[lane + 32] = v1 * mult;
}

// ---------------------------------------------------------------------------
// Flash attention, fp16x3 tensor cores.
// Block: 64 q-rows x one (b,h). 128 threads (4 warps); warp owns 16 rows.
// K smem [key][dpair] stride 36; V smem key-paired [kp][d] stride 72.
// P fragments built register-side (C-frag == A-frag layout for k16).
// ---------------------------------------------------------------------------
__global__ __launch_bounds__(128) void attn_f16() {
    __shared__ uint32_t Kpb[64][36], Kps[64][36];   // [key][dp]
    __shared__ uint32_t Vpb[32][72], Vps[32][72];   // [kp][d]

    const int tid  = threadIdx.x;
    const int warp = tid >> 5, lane = tid & 31;
    const int gid = lane >> 2, tig = lane & 3;
    const int rowbase = warp << 4;

    const int qt  = gridDim.x - 1 - blockIdx.x;    // heavy tiles first
    const int bh  = blockIdx.y;
    const int b   = bh >> 3, h = bh & 7, kvh = h >> 1;
    const float NEG = -CUDART_INF_F;

    // Q fragments (16 rows x 64 d per warp), big/small packed half2
    uint32_t qb[4][4], qs[4][4];
    const float* qptr = g_q + (size_t)(b * TT + qt * 64 + rowbase) * DD + h * HD;
#pragma unroll
    for (int ks = 0; ks < 4; ks++) {
        int c0 = (ks << 4) + (tig << 1);
        const float* r0p = qptr + (size_t)gid * DD;
        const float* r1p = qptr + (size_t)(gid + 8) * DD;
        split2(r0p[c0],     r0p[c0 + 1], qb[ks][0], qs[ks][0]);
        split2(r1p[c0],     r1p[c0 + 1], qb[ks][1], qs[ks][1]);
        split2(r0p[c0 + 8], r0p[c0 + 9], qb[ks][2], qs[ks][2]);
        split2(r1p[c0 + 8], r1p[c0 + 9], qb[ks][3], qs[ks][3]);
    }

    float oacc[8][4] = {};
    float m0 = NEG, m1 = NEG, l0 = 0.0f, l1 = 0.0f;

    const float* kbase = g_k + ((size_t)(b * TT) * NKV + kvh) * HD;
    const float* vbase = g_v + ((size_t)(b * TT) * NKV + kvh) * HD;

    const int vd = tid & 63, vkh = tid >> 6;       // V loader mapping

    for (int kt = 0; kt <= qt; kt++) {
        __syncthreads();                           // all warps done with tiles
        const float* kp_ = kbase + (size_t)kt * 64 * (NKV * HD);
        const float* vp_ = vbase + (size_t)kt * 64 * (NKV * HD);
        // K tile: [key][dpair]
#pragma unroll
        for (int i = 0; i < 8; i++) {
            int idx = tid + (i << 7);
            int r = idx >> 4, c4 = idx & 15;
            float4 kv = *(const float4*)(kp_ + (size_t)r * (NKV * HD) + (c4 << 2));
            uint32_t b0, s0, b1, s1;
            split2(kv.x, kv.y, b0, s0); split2(kv.z, kv.w, b1, s1);
            *(uint2*)&Kpb[r][c4 << 1] = make_uint2(b0, b1);
            *(uint2*)&Kps[r][c4 << 1] = make_uint2(s0, s1);
        }
        // V tile: key-paired transpose [kp][d]
        {
            const float* vcol = vp_ + vd;
#pragma unroll
            for (int j = 0; j < 16; j++) {
                int key0 = (vkh << 5) + (j << 1);
                float v0 = vcol[(size_t)key0 * (NKV * HD)];
                float v1 = vcol[(size_t)(key0 + 1) * (NKV * HD)];
                uint32_t bb, ss;
                split2(v0, v1, bb, ss);
                Vpb[(vkh << 4) + j][vd] = bb;
                Vps[(vkh << 4) + j][vd] = ss;
            }
        }
        __syncthreads();

        // S = Q K^T  (fp16x3)
        float sacc[8][4] = {};
#pragma unroll
        for (int ks = 0; ks < 4; ks++) {
            int dp = (ks << 3) + tig;
#pragma unroll
            for (int nt = 0; nt < 8; nt++) {
                int key = (nt << 3) + gid;
                uint32_t kb0 = Kpb[key][dp], kb1 = Kpb[key][dp + 4];
                uint32_t ks0 = Kps[key][dp], ks1 = Kps[key][dp + 4];
                mma_f16(sacc[nt], qb[ks][0], qb[ks][1], qb[ks][2], qb[ks][3], kb0, kb1);
                mma_f16(sacc[nt], qb[ks][0], qb[ks][1], qb[ks][2], qb[ks][3], ks0, ks1);
                mma_f16(sacc[nt], qs[ks][0], qs[ks][1], qs[ks][2], qs[ks][3], kb0, kb1);
            }
        }

        if (kt == qt) {                            // causal mask on diagonal tile
            int r0 = rowbase + gid, r1 = r0 + 8;
#pragma unroll
            for (int nt = 0; nt < 8; nt++) {
                int c0 = (nt << 3) + (tig << 1), c1 = c0 + 1;
                if (c0 > r0) sacc[nt][0] = NEG;
                if (c1 > r0) sacc[nt][1] = NEG;
                if (c0 > r1) sacc[nt][2] = NEG;
                if (c1 > r1) sacc[nt][3] = NEG;
            }
        }

        // online softmax (rows rowbase+gid, rowbase+gid+8)
        float mt0 = NEG, mt1 = NEG;
#pragma unroll
        for (int nt = 0; nt < 8; nt++) {
            mt0 = fmaxf(mt0, fmaxf(sacc[nt][0], sacc[nt][1]));
            mt1 = fmaxf(mt1, fmaxf(sacc[nt][2], sacc[nt][3]));
        }
        mt0 = fmaxf(mt0, __shfl_xor_sync(0xffffffffu, mt0, 1));
        mt0 = fmaxf(mt0, __shfl_xor_sync(0xffffffffu, mt0, 2));
        mt1 = fmaxf(mt1, __shfl_xor_sync(0xffffffffu, mt1, 1));
        mt1 = fmaxf(mt1, __shfl_xor_sync(0xffffffffu, mt1, 2));

        float mn0 = fmaxf(m0, mt0), mn1 = fmaxf(m1, mt1);
        float al0 = __expf(m0 - mn0), al1 = __expf(m1 - mn1);
        m0 = mn0; m1 = mn1;

        float rs0 = 0.0f, rs1 = 0.0f;
#pragma unroll
        for (int nt = 0; nt < 8; nt++) {
            sacc[nt][0] = __expf(sacc[nt][0] - m0);
            sacc[nt][1] = __expf(sacc[nt][1] - m0);
            sacc[nt][2] = __expf(sacc[nt][2] - m1);
            sacc[nt][3] = __expf(sacc[nt][3] - m1);
            rs0 += sacc[nt][0] + sacc[nt][1];
            rs1 += sacc[nt][2] + sacc[nt][3];
        }
        rs0 += __shfl_xor_sync(0xffffffffu, rs0, 1);
        rs0 += __shfl_xor_sync(0xffffffffu, rs0, 2);
        rs1 += __shfl_xor_sync(0xffffffffu, rs1, 1);
        rs1 += __shfl_xor_sync(0xffffffffu, rs1, 2);
        l0 = l0 * al0 + rs0;
        l1 = l1 * al1 + rs1;
#pragma unroll
        for (int nt = 0; nt < 8; nt++) {
            oacc[nt][0] *= al0; oacc[nt][1] *= al0;
            oacc[nt][2] *= al1; oacc[nt][3] *= al1;
        }

        // O += P V  (fp16x3, P fragments from registers)
#pragma unroll
        for (int ks = 0; ks < 4; ks++) {
            uint32_t pb[4], ps[4];
            split2(sacc[2*ks][0],     sacc[2*ks][1],     pb[0], ps[0]);
            split2(sacc[2*ks][2],     sacc[2*ks][3],     pb[1], ps[1]);
            split2(sacc[2*ks + 1][0], sacc[2*ks + 1][1], pb[2], ps[2]);
            split2(sacc[2*ks + 1][2], sacc[2*ks + 1][3], pb[3], ps[3]);
            int kp = (ks << 3) + tig;
#pragma unroll
            for (int nt = 0; nt < 8; nt++) {
                int d = (nt << 3) + gid;
                uint32_t vb0 = Vpb[kp][d], vb1 = Vpb[kp + 4][d];
                uint32_t vs0 = Vps[kp][d], vs1 = Vps[kp + 4][d];
                mma_f16(oacc[nt], pb[0], pb[1], pb[2], pb[3], vb0, vb1);
                mma_f16(oacc[nt], pb[0], pb[1], pb[2], pb[3], vs0, vs1);
                mma_f16(oacc[nt], ps[0], ps[1], ps[2], ps[3], vb0, vb1);
            }
        }
    }

    float inv0 = 1.0f / l0, inv1 = 1.0f / l1;
    float* yp = g_y + (size_t)(b * TT + qt * 64) * DD + h * HD;
    int r0 = rowbase + gid, r1 = r0 + 8;
#pragma unroll
    for (int nt = 0; nt < 8; nt++) {
        int c = (nt << 3) + (tig << 1);
        *(float2*)(yp + (size_t)r0 * DD + c) =
            make_float2(oacc[nt][0] * inv0, oacc[nt][1] * inv0);
        *(float2*)(yp + (size_t)r1 * DD + c) =
            make_float2(oacc[nt][2] * inv1, oacc[nt][3] * inv1);
    }
}

// ---------------------------------------------------------------------------
extern "C" void kernel_launch(void* const* d_in, const int* in_sizes, int n_in,
                              void* d_out, int out_size) {
    (void)in_sizes; (void)n_in; (void)out_size;
    const float* x      = (const float*)d_in[0];
    const float* w_q    = (const float*)d_in[1];
    const float* w_k    = (const float*)d_in[2];
    const float* w_v    = (const float*)d_in[3];
    const float* w_proj = (const float*)d_in[4];
    const float* q_gain = (const float*)d_in[5];
    float* out = (float*)d_out;

    void* p;
    cudaGetSymbolAddress(&p, g_q); float* gq = (float*)p;
    cudaGetSymbolAddress(&p, g_k); float* gk = (float*)p;
    cudaGetSymbolAddress(&p, g_v); float* gv = (float*)p;
    cudaGetSymbolAddress(&p, g_y); float* gy = (float*)p;

    sgemm_f16<<<dim3(8, 128), 256>>>(x, w_q, gq, 512);
    sgemm_f16<<<dim3(4, 128), 256>>>(x, w_k, gk, 256);
    sgemm_f16<<<dim3(4, 128), 256>>>(x, w_v, gv, 256);

    normrope_kernel<<<(NTOK * (NH + NKV)) / 8, 256>>>(q_gain);

    attn_f16<<<dim3(TT / 64, BB * NH), 128>>>();

    sgemm_f16<<<dim3(8, 128), 256>>>(gy, w_proj, out, 512);
}

// round 7
// speedup vs baseline: 3.0639x; 1.0852x over previous
#include <cuda_runtime.h>
#include <cuda_fp16.h>
#include <math_constants.h>
#include <cstdint>

#define BB   4
#define TT   2048
#define DD   512
#define NH   8
#define NKV  4
#define HD   64
#define NTOK (BB*TT)          // 8192

// ---------------- scratch (device globals: allocation-free) ----------------
__device__ float g_q[(size_t)NTOK * DD];
__device__ float g_k[(size_t)NTOK * NKV * HD];
__device__ float g_v[(size_t)NTOK * NKV * HD];
__device__ float g_y[(size_t)NTOK * DD];

// ------------------------------ helpers ------------------------------------
// split (x,y) into fp16 big/small packed half2 pairs (fp16x3 decomposition)
__device__ __forceinline__ void split2(float x, float y, uint32_t& b, uint32_t& s) {
    __half hbx = __float2half_rn(x);
    __half hby = __float2half_rn(y);
    float rx = x - __half2float(hbx);
    float ry = y - __half2float(hby);
    __half2 hb = __halves2half2(hbx, hby);
    __half2 hs = __halves2half2(__float2half_rn(rx), __float2half_rn(ry));
    b = *reinterpret_cast<uint32_t*>(&hb);
    s = *reinterpret_cast<uint32_t*>(&hs);
}

__device__ __forceinline__ float fexp2(float x) {
    float y;
    asm("ex2.approx.f32 %0, %1;" : "=f"(y) : "f"(x));
    return y;
}

__device__ __forceinline__ void mma_f16(float c[4], uint32_t a0, uint32_t a1,
                                        uint32_t a2, uint32_t a3,
                                        uint32_t b0, uint32_t b1) {
    asm volatile(
        "mma.sync.aligned.m16n8k16.row.col.f32.f16.f16.f32 "
        "{%0,%1,%2,%3},{%4,%5,%6,%7},{%8,%9},{%0,%1,%2,%3};"
        : "+f"(c[0]), "+f"(c[1]), "+f"(c[2]), "+f"(c[3])
        : "r"(a0), "r"(a1), "r"(a2), "r"(a3), "r"(b0), "r"(b1));
}

// ---------------------------------------------------------------------------
// fp16x3 GEMM body (NT): C[n,m] = sum_d A[n,d]*W[m,d].  BM=BN=64, BK=32,
// 256 threads (8 warps), warp grid 2x4, warp tile 32x16.
// Register-prefetch double buffering over the 16 k-blocks.
// ---------------------------------------------------------------------------
__device__ __forceinline__ void gemm_body(const float* __restrict__ A,
                                          const float* __restrict__ W,
                                          float* __restrict__ C, int M,
                                          int rb, int cb) {
    __shared__ __align__(16) uint32_t Ab[64][20], As_[64][20];
    __shared__ __align__(16) uint32_t Wb[64][20], Ws_[64][20];
    const int tid  = threadIdx.x;
    const int warp = tid >> 5, lane = tid & 31;
    const int gid = lane >> 2, tig = lane & 3;
    const int wm = warp >> 2, wn = warp & 3;

    const float* Ap = A + (size_t)rb * DD;
    const float* Wp = W + (size_t)cb * DD;

    // prefetch first k-block into registers
    float4 pa[2], pw[2];
#pragma unroll
    for (int i = 0; i < 2; i++) {
        int idx = tid + (i << 8);
        int rr = idx >> 3, cc = idx & 7;
        pa[i] = *(const float4*)(Ap + (size_t)rr * DD + (cc << 2));
        pw[i] = *(const float4*)(Wp + (size_t)rr * DD + (cc << 2));
    }

    float acc[2][2][4] = {};

    for (int k0 = 0; k0 < DD; k0 += 32) {
        // split + store the prefetched block
#pragma unroll
        for (int i = 0; i < 2; i++) {
            int idx = tid + (i << 8);
            int rr = idx >> 3, cc = idx & 7;
            uint32_t b0, s0, b1, s1;
            split2(pa[i].x, pa[i].y, b0, s0); split2(pa[i].z, pa[i].w, b1, s1);
            *(uint2*)&Ab[rr][cc << 1]  = make_uint2(b0, b1);
            *(uint2*)&As_[rr][cc << 1] = make_uint2(s0, s1);
            split2(pw[i].x, pw[i].y, b0, s0); split2(pw[i].z, pw[i].w, b1, s1);
            *(uint2*)&Wb[rr][cc << 1]  = make_uint2(b0, b1);
            *(uint2*)&Ws_[rr][cc << 1] = make_uint2(s0, s1);
        }
        __syncthreads();

        // issue next block's loads (hidden behind MMA phase)
        if (k0 + 32 < DD) {
#pragma unroll
            for (int i = 0; i < 2; i++) {
                int idx = tid + (i << 8);
                int rr = idx >> 3, cc = idx & 7;
                pa[i] = *(const float4*)(Ap + (size_t)rr * DD + k0 + 32 + (cc << 2));
                pw[i] = *(const float4*)(Wp + (size_t)rr * DD + k0 + 32 + (cc << 2));
            }
        }

#pragma unroll
        for (int ks = 0; ks < 2; ks++) {
            int dp = (ks << 3) + tig;
            uint32_t ab[2][4], as[2][4];
#pragma unroll
            for (int mt = 0; mt < 2; mt++) {
                int row = (wm << 5) + (mt << 4) + gid;
                ab[mt][0] = Ab[row][dp];      ab[mt][1] = Ab[row + 8][dp];
                ab[mt][2] = Ab[row][dp + 4];  ab[mt][3] = Ab[row + 8][dp + 4];
                as[mt][0] = As_[row][dp];     as[mt][1] = As_[row + 8][dp];
                as[mt][2] = As_[row][dp + 4]; as[mt][3] = As_[row + 8][dp + 4];
            }
#pragma unroll
            for (int nt = 0; nt < 2; nt++) {
                int nrow = (wn << 4) + (nt << 3) + gid;
                uint32_t bb0 = Wb[nrow][dp],  bb1 = Wb[nrow][dp + 4];
                uint32_t bs0 = Ws_[nrow][dp], bs1 = Ws_[nrow][dp + 4];
#pragma unroll
                for (int mt = 0; mt < 2; mt++) {
                    mma_f16(acc[mt][nt], ab[mt][0], ab[mt][1], ab[mt][2], ab[mt][3], bb0, bb1);
                    mma_f16(acc[mt][nt], ab[mt][0], ab[mt][1], ab[mt][2], ab[mt][3], bs0, bs1);
                    mma_f16(acc[mt][nt], as[mt][0], as[mt][1], as[mt][2], as[mt][3], bb0, bb1);
                }
            }
        }
        __syncthreads();
    }
#pragma unroll
    for (int mt = 0; mt < 2; mt++)
#pragma unroll
        for (int nt = 0; nt < 2; nt++) {
            int row = rb + (wm << 5) + (mt << 4) + gid;
            int col = cb + (wn << 4) + (nt << 3) + (tig << 1);
            *(float2*)(C + (size_t)row * M + col)       = make_float2(acc[mt][nt][0], acc[mt][nt][1]);
            *(float2*)(C + (size_t)(row + 8) * M + col) = make_float2(acc[mt][nt][2], acc[mt][nt][3]);
        }
}

// Fused QKV projections: blockIdx.x selects target matrix + column tile.
__global__ __launch_bounds__(256) void qkv_gemm(const float* __restrict__ x,
                                                const float* __restrict__ w_q,
                                                const float* __restrict__ w_k,
                                                const float* __restrict__ w_v,
                                                float* __restrict__ gq,
                                                float* __restrict__ gk,
                                                float* __restrict__ gv) {
    const int bx = blockIdx.x;
    const float* W;
    float* C;
    int M, cb;
    if (bx < 8)       { W = w_q; C = gq; M = 512; cb = bx << 6; }
    else if (bx < 12) { W = w_k; C = gk; M = 256; cb = (bx - 8) << 6; }
    else              { W = w_v; C = gv; M = 256; cb = (bx - 12) << 6; }
    gemm_body(x, W, C, M, blockIdx.y << 6, cb);
}

__global__ __launch_bounds__(256) void sgemm_f16(const float* __restrict__ A,
                                                 const float* __restrict__ W,
                                                 float* __restrict__ C, int M) {
    gemm_body(A, W, C, M, blockIdx.y << 6, blockIdx.x << 6);
}

// ---------------------------------------------------------------------------
// Fused RMSNorm + RoPE + gain (q) / RMSNorm + RoPE (k), in place.
// Folds softmax scale 1/8 AND log2(e) into q (softmax runs in exp2 domain).
// ---------------------------------------------------------------------------
__global__ __launch_bounds__(256) void normrope_kernel(const float* __restrict__ qg) {
    const int w    = (blockIdx.x * blockDim.x + threadIdx.x) >> 5;
    const int lane = threadIdx.x & 31;
    const int NQ = NTOK * NH;
    float* p;
    int pos;
    float mult;
    if (w < NQ) {
        int tok = w >> 3, hh = w & 7;
        p    = g_q + (size_t)tok * DD + hh * HD;
        pos  = tok & (TT - 1);
        mult = qg[hh] * 0.125f * 1.44269504088896340736f;   // gain/sqrt(64)*log2e
    } else {
        int w2 = w - NQ;
        if (w2 >= NTOK * NKV) return;
        int tok = w2 >> 2, kv = w2 & 3;
        p    = g_k + (size_t)tok * (NKV * HD) + kv * HD;
        pos  = tok & (TT - 1);
        mult = 1.0f;
    }
    float v0 = p[lane];
    float v1 = p[lane + 32];
    float ss = v0 * v0 + v1 * v1;
#pragma unroll
    for (int o = 16; o > 0; o >>= 1) ss += __shfl_xor_sync(0xffffffffu, ss, o);
    const float rn = rsqrtf(ss * (1.0f / 64.0f) + 1.1920929e-7f);
    v0 *= rn; v1 *= rn;

    float other = __shfl_xor_sync(0xffffffffu, v0, 8);
    float r0 = v0;
    if (lane < 16) {
        int   fi   = lane & 7;
        float invf = powf(10000.0f, -(float)fi * 0.125f);
        float ang  = (float)pos * invf;
        float sn, cs;
        sincosf(ang, &sn, &cs);
        r0 = (lane < 8) ? (v0 * cs + other * sn) : (v0 * cs - other * sn);
    }
    p[lane]      = r0 * mult;
    p[lane + 32] = v1 * mult;
}

// ---------------------------------------------------------------------------
// Flash attention, fp16x3 tensor cores, exp2-domain softmax.
// Block: 64 q-rows x one (b,h). 128 threads (4 warps); warp owns 16 rows.
// K smem [key][dpair] stride 36; V smem key-paired [kp][d] stride 72
// (float4-based pairing loader: 8 LDG.128 + 8 STS.128 per thread per tile).
// P fragments built register-side (C-frag == A-frag layout for k16).
// ---------------------------------------------------------------------------
__global__ __launch_bounds__(128) void attn_f16() {
    __shared__ __align__(16) uint32_t Kpb[64][36], Kps[64][36];   // [key][dp]
    __shared__ __align__(16) uint32_t Vpb[32][72], Vps[32][72];   // [kp][d]

    const int tid  = threadIdx.x;
    const int warp = tid >> 5, lane = tid & 31;
    const int gid = lane >> 2, tig = lane & 3;
    const int rowbase = warp << 4;

    const int qt  = gridDim.x - 1 - blockIdx.x;    // heavy tiles first
    const int bh  = blockIdx.y;
    const int b   = bh >> 3, h = bh & 7, kvh = h >> 1;
    const float NEG = -CUDART_INF_F;

    // Q fragments (16 rows x 64 d per warp), big/small packed half2
    uint32_t qb[4][4], qs[4][4];
    const float* qptr = g_q + (size_t)(b * TT + qt * 64 + rowbase) * DD + h * HD;
#pragma unroll
    for (int ks = 0; ks < 4; ks++) {
        int c0 = (ks << 4) + (tig << 1);
        const float* r0p = qptr + (size_t)gid * DD;
        const float* r1p = qptr + (size_t)(gid + 8) * DD;
        split2(r0p[c0],     r0p[c0 + 1], qb[ks][0], qs[ks][0]);
        split2(r1p[c0],     r1p[c0 + 1], qb[ks][1], qs[ks][1]);
        split2(r0p[c0 + 8], r0p[c0 + 9], qb[ks][2], qs[ks][2]);
        split2(r1p[c0 + 8], r1p[c0 + 9], qb[ks][3], qs[ks][3]);
    }

    float oacc[8][4] = {};
    float m0 = NEG, m1 = NEG, l0 = 0.0f, l1 = 0.0f;

    const float* kbase = g_k + ((size_t)(b * TT) * NKV + kvh) * HD;
    const float* vbase = g_v + ((size_t)(b * TT) * NKV + kvh) * HD;

    for (int kt = 0; kt <= qt; kt++) {
        __syncthreads();                           // all warps done with tiles
        const float* kp_ = kbase + (size_t)kt * 64 * (NKV * HD);
        const float* vp_ = vbase + (size_t)kt * 64 * (NKV * HD);
        // K tile: [key][dpair]
#pragma unroll
        for (int i = 0; i < 8; i++) {
            int idx = tid + (i << 7);
            int r = idx >> 4, c4 = idx & 15;
            float4 kv = *(const float4*)(kp_ + (size_t)r * (NKV * HD) + (c4 << 2));
            uint32_t b0, s0, b1, s1;
            split2(kv.x, kv.y, b0, s0); split2(kv.z, kv.w, b1, s1);
            *(uint2*)&Kpb[r][c4 << 1] = make_uint2(b0, b1);
            *(uint2*)&Kps[r][c4 << 1] = make_uint2(s0, s1);
        }
        // V tile: key-paired [kp][d], float4-based pairing
        {
            int d   = (tid & 15) << 2;
            int kp8 = tid >> 4;                    // 0..7
#pragma unroll
            for (int it = 0; it < 4; it++) {
                int kp = (it << 3) + kp8;
                const float* r0 = vp_ + (size_t)(kp << 1) * (NKV * HD) + d;
                float4 v0 = *(const float4*)r0;
                float4 v1 = *(const float4*)(r0 + NKV * HD);
                uint32_t b0, s0, b1, s1, b2, s2, b3, s3;
                split2(v0.x, v1.x, b0, s0);
                split2(v0.y, v1.y, b1, s1);
                split2(v0.z, v1.z, b2, s2);
                split2(v0.w, v1.w, b3, s3);
                *(uint4*)&Vpb[kp][d] = make_uint4(b0, b1, b2, b3);
                *(uint4*)&Vps[kp][d] = make_uint4(s0, s1, s2, s3);
            }
        }
        __syncthreads();

        // S = Q K^T  (fp16x3) -- S already in log2 domain (log2e folded into q)
        float sacc[8][4] = {};
#pragma unroll
        for (int ks = 0; ks < 4; ks++) {
            int dp = (ks << 3) + tig;
#pragma unroll
            for (int nt = 0; nt < 8; nt++) {
                int key = (nt << 3) + gid;
                uint32_t kb0 = Kpb[key][dp], kb1 = Kpb[key][dp + 4];
                uint32_t ks0 = Kps[key][dp], ks1 = Kps[key][dp + 4];
                mma_f16(sacc[nt], qb[ks][0], qb[ks][1], qb[ks][2], qb[ks][3], kb0, kb1);
                mma_f16(sacc[nt], qb[ks][0], qb[ks][1], qb[ks][2], qb[ks][3], ks0, ks1);
                mma_f16(sacc[nt], qs[ks][0], qs[ks][1], qs[ks][2], qs[ks][3], kb0, kb1);
            }
        }

        if (kt == qt) {                            // causal mask on diagonal tile
            int r0 = rowbase + gid, r1 = r0 + 8;
#pragma unroll
            for (int nt = 0; nt < 8; nt++) {
                int c0 = (nt << 3) + (tig << 1), c1 = c0 + 1;
                if (c0 > r0) sacc[nt][0] = NEG;
                if (c1 > r0) sacc[nt][1] = NEG;
                if (c0 > r1) sacc[nt][2] = NEG;
                if (c1 > r1) sacc[nt][3] = NEG;
            }
        }

        // online softmax in exp2 domain (rows rowbase+gid, rowbase+gid+8)
        float mt0 = NEG, mt1 = NEG;
#pragma unroll
        for (int nt = 0; nt < 8; nt++) {
            mt0 = fmaxf(mt0, fmaxf(sacc[nt][0], sacc[nt][1]));
            mt1 = fmaxf(mt1, fmaxf(sacc[nt][2], sacc[nt][3]));
        }
        mt0 = fmaxf(mt0, __shfl_xor_sync(0xffffffffu, mt0, 1));
        mt0 = fmaxf(mt0, __shfl_xor_sync(0xffffffffu, mt0, 2));
        mt1 = fmaxf(mt1, __shfl_xor_sync(0xffffffffu, mt1, 1));
        mt1 = fmaxf(mt1, __shfl_xor_sync(0xffffffffu, mt1, 2));

        float mn0 = fmaxf(m0, mt0), mn1 = fmaxf(m1, mt1);
        float al0 = fexp2(m0 - mn0), al1 = fexp2(m1 - mn1);
        m0 = mn0; m1 = mn1;

        float rs0 = 0.0f, rs1 = 0.0f;
#pragma unroll
        for (int nt = 0; nt < 8; nt++) {
            sacc[nt][0] = fexp2(sacc[nt][0] - m0);
            sacc[nt][1] = fexp2(sacc[nt][1] - m0);
            sacc[nt][2] = fexp2(sacc[nt][2] - m1);
            sacc[nt][3] = fexp2(sacc[nt][3] - m1);
            rs0 += sacc[nt][0] + sacc[nt][1];
            rs1 += sacc[nt][2] + sacc[nt][3];
        }
        rs0 += __shfl_xor_sync(0xffffffffu, rs0, 1);
        rs0 += __shfl_xor_sync(0xffffffffu, rs0, 2);
        rs1 += __shfl_xor_sync(0xffffffffu, rs1, 1);
        rs1 += __shfl_xor_sync(0xffffffffu, rs1, 2);
        l0 = l0 * al0 + rs0;
        l1 = l1 * al1 + rs1;
#pragma unroll
        for (int nt = 0; nt < 8; nt++) {
            oacc[nt][0] *= al0; oacc[nt][1] *= al0;
            oacc[nt][2] *= al1; oacc[nt][3] *= al1;
        }

        // O += P V  (fp16x3, P fragments from registers)
#pragma unroll
        for (int ks = 0; ks < 4; ks++) {
            uint32_t pb[4], ps[4];
            split2(sacc[2*ks][0],     sacc[2*ks][1],     pb[0], ps[0]);
            split2(sacc[2*ks][2],     sacc[2*ks][3],     pb[1], ps[1]);
            split2(sacc[2*ks + 1][0], sacc[2*ks + 1][1], pb[2], ps[2]);
            split2(sacc[2*ks + 1][2], sacc[2*ks + 1][3], pb[3], ps[3]);
            int kp = (ks << 3) + tig;
#pragma unroll
            for (int nt = 0; nt < 8; nt++) {
                int d = (nt << 3) + gid;
                uint32_t vb0 = Vpb[kp][d], vb1 = Vpb[kp + 4][d];
                uint32_t vs0 = Vps[kp][d], vs1 = Vps[kp + 4][d];
                mma_f16(oacc[nt], pb[0], pb[1], pb[2], pb[3], vb0, vb1);
                mma_f16(oacc[nt], pb[0], pb[1], pb[2], pb[3], vs0, vs1);
                mma_f16(oacc[nt], ps[0], ps[1], ps[2], ps[3], vb0, vb1);
            }
        }
    }

    float inv0 = 1.0f / l0, inv1 = 1.0f / l1;
    float* yp = g_y + (size_t)(b * TT + qt * 64) * DD + h * HD;
    int r0 = rowbase + gid, r1 = r0 + 8;
#pragma unroll
    for (int nt = 0; nt < 8; nt++) {
        int c = (nt << 3) + (tig << 1);
        *(float2*)(yp + (size_t)r0 * DD + c) =
            make_float2(oacc[nt][0] * inv0, oacc[nt][1] * inv0);
        *(float2*)(yp + (size_t)r1 * DD + c) =
            make_float2(oacc[nt][2] * inv1, oacc[nt][3] * inv1);
    }
}

// ---------------------------------------------------------------------------
extern "C" void kernel_launch(void* const* d_in, const int* in_sizes, int n_in,
                              void* d_out, int out_size) {
    (void)in_sizes; (void)n_in; (void)out_size;
    const float* x      = (const float*)d_in[0];
    const float* w_q    = (const float*)d_in[1];
    const float* w_k    = (const float*)d_in[2];
    const float* w_v    = (const float*)d_in[3];
    const float* w_proj = (const float*)d_in[4];
    const float* q_gain = (const float*)d_in[5];
    float* out = (float*)d_out;

    void* p;
    cudaGetSymbolAddress(&p, g_q); float* gq = (float*)p;
    cudaGetSymbolAddress(&p, g_k); float* gk = (float*)p;
    cudaGetSymbolAddress(&p, g_v); float* gv = (float*)p;
    cudaGetSymbolAddress(&p, g_y); float* gy = (float*)p;

    qkv_gemm<<<dim3(16, 128), 256>>>(x, w_q, w_k, w_v, gq, gk, gv);

    normrope_kernel<<<(NTOK * (NH + NKV)) / 8, 256>>>(q_gain);

    attn_f16<<<dim3(TT / 64, BB * NH), 128>>>();

    sgemm_f16<<<dim3(8, 128), 256>>>(gy, w_proj, out, 512);
}